// round 11
// baseline (speedup 1.0000x reference)
#include <cuda_runtime.h>
#include <cuda_bf16.h>
#include <math.h>

#define NTOK 4096
#define HDIM 128
#define NHEAD 8
#define HEADD 16
#define FFDIM 256
#define NLAYER 4
#define QKVDIM 384
#define LATD 16
#define MAXN 512
#define BK 16

// binning
#define EB 26
#define PB 31
#define NCELL (EB * PB)
#define ETA_MIN (-2.62f)
#define PHI_MIN (-3.1416f)
#define ETA_INV (26.0f / 5.24f)
#define PHI_INV (31.0f / 6.2832f)

// ---------------- scratch (device globals; no runtime allocation) ----------------
__device__ float g_x[NTOK * HDIM];
__device__ float g_qkv[NTOK * QKVDIM];
__device__ float g_attn[NTOK * HDIM];
__device__ float g_ff[NTOK * FFDIM];
__device__ float g_mean[NTOK];
__device__ float g_rstd[NTOK];
__device__ float g_eta[NTOK];
__device__ float g_phi[NTOK];
__device__ int   g_nbr[NTOK * MAXN];
__device__ int   g_cnt[NTOK];
__device__ int   g_cellcnt[NCELL];
__device__ int   g_celloff[NCELL];
__device__ int   g_cellstart[NCELL + 1];
__device__ int   g_cellidx[NTOK];
__device__ int   g_tokbin[NTOK];

// ---------------- binning pipeline ----------------
__global__ void zero_cells_kernel() {
    int i = blockIdx.x * blockDim.x + threadIdx.x;
    if (i < NCELL) g_cellcnt[i] = 0;
}

__global__ void etaphi_bin_kernel(const float* __restrict__ x_raw) {
    int i = blockIdx.x * blockDim.x + threadIdx.x;
    if (i >= NTOK) return;
    float eta = __ldg(&x_raw[i * 16 + 1]) * 5.24f + (-2.62f);
    float phi = __ldg(&x_raw[i * 16 + 2]) * 6.2832f + (-3.1416f);
    g_eta[i] = eta;
    g_phi[i] = phi;
    int eb = (int)((eta - ETA_MIN) * ETA_INV);
    eb = max(0, min(eb, EB - 1));
    int pb = (int)((phi - PHI_MIN) * PHI_INV);
    pb = ((pb % PB) + PB) % PB;
    int bin = eb * PB + pb;
    g_tokbin[i] = bin;
    atomicAdd(&g_cellcnt[bin], 1);
}

// single-block inclusive scan over NCELL (806) entries
__global__ void prefix_kernel() {
    __shared__ int sc[1024];
    int t = threadIdx.x;
    sc[t] = (t < NCELL) ? g_cellcnt[t] : 0;
    __syncthreads();
    #pragma unroll
    for (int o = 1; o < 1024; o <<= 1) {
        int v = (t >= o) ? sc[t - o] : 0;
        __syncthreads();
        sc[t] += v;
        __syncthreads();
    }
    if (t < NCELL) {
        g_cellstart[t + 1] = sc[t];
        g_celloff[t] = 0;
    }
    if (t == 0) g_cellstart[0] = 0;
}

__global__ void scatter_kernel() {
    int i = blockIdx.x * blockDim.x + threadIdx.x;
    if (i >= NTOK) return;
    int bin = g_tokbin[i];
    int pos = g_cellstart[bin] + atomicAdd(&g_celloff[bin], 1);
    g_cellidx[pos] = i;
}

// one warp per query: scan 3x3 cells, exact dr check, ballot-compacted append
__global__ void nbr_warp_kernel() {
    int warp = blockIdx.x * (blockDim.x >> 5) + (threadIdx.x >> 5);
    int lane = threadIdx.x & 31;
    if (warp >= NTOK) return;
    const int i = warp;
    const float ei = g_eta[i], pii = g_phi[i];

    int eb = (int)((ei - ETA_MIN) * ETA_INV);
    eb = max(0, min(eb, EB - 1));
    int pb = (int)((pii - PHI_MIN) * PHI_INV);
    pb = ((pb % PB) + PB) % PB;

    int cnt = 0;
    int* list = &g_nbr[i * MAXN];

    const int elo = max(eb - 1, 0), ehi = min(eb + 1, EB - 1);
    for (int ce = elo; ce <= ehi; ce++) {
        #pragma unroll
        for (int dp = -1; dp <= 1; dp++) {
            int cp = pb + dp;
            cp = (cp + PB) % PB;
            int c = ce * PB + cp;
            int s = g_cellstart[c], e = g_cellstart[c + 1];
            for (int t = s; t < e; t += 32) {
                int idx = t + lane;
                bool pass = false;
                int j = -1;
                if (idx < e) {
                    j = g_cellidx[idx];
                    float de = ei - g_eta[j];
                    float dpr = pii - g_phi[j];
                    // exact check, mirroring reference computation order in fp32
                    float dphi = atan2f(sinf(dpr), cosf(dpr));
                    float s2 = __fadd_rn(__fmul_rn(de, de), __fmul_rn(dphi, dphi));
                    pass = (sqrtf(s2) <= 0.2f);
                }
                unsigned msk = __ballot_sync(0xffffffffu, pass);
                if (pass) {
                    int rank = __popc(msk & ((1u << lane) - 1));
                    int p = cnt + rank;
                    if (p < MAXN) list[p] = j;
                }
                cnt += __popc(msk);
            }
        }
    }
    if (lane == 0) g_cnt[i] = (cnt < MAXN) ? cnt : MAXN;
}

// =================================================================================
// gemm2: 32x128 tile, 4x4 microtile (warp owns full rows) — used where STATS/RES
//   needed or shapes are small.  C = op(A) @ W^T + bias (+ReLU) (+res g_x)
// =================================================================================
template <int M, int NC, int K, int BM, int BN,
          int LNA, int RELU, int RES, int STATS, int SRC, int DST>
__global__ __launch_bounds__(256) void gemm2(
    const float* __restrict__ Aext, const float* __restrict__ W,
    const float* __restrict__ bias,
    const float* __restrict__ ln_s, const float* __restrict__ ln_b) {

    constexpr int TN = BN / 4;
    constexpr int TM = 256 / TN;
    static_assert(TM * 4 == BM && TN * 4 == BN, "tile mismatch");
    constexpr int AF = BM * BK / 256;
    constexpr int WF = BN * BK / 256;
    constexpr int NK = K / BK;

    __shared__ float As[2][BK][BM + 4];
    __shared__ float Ws[2][BK][BN + 4];

    const float* A = (SRC == 0) ? Aext : (SRC == 1) ? g_x : (SRC == 2) ? g_attn : g_ff;
    float* C = (DST == 0) ? g_x : (DST == 1) ? g_qkv : g_ff;

    const int tid = threadIdx.x;
    const int m0 = blockIdx.y * BM, n0 = blockIdx.x * BN;
    const int tm = tid / TN, tn = tid % TN;

    const int arow = tid / (BK / AF);
    const int acol = (tid % (BK / AF)) * AF;
    const int wrow = tid / (BK / WF);
    const int wcol = (tid % (BK / WF)) * WF;

    const int agr = m0 + arow;
    const int wgr = n0 + wrow;
    float amu = 0.f, ars = 0.f;
    if (LNA) { amu = g_mean[agr]; ars = g_rstd[agr]; }

    float pa[AF], pw[WF];

    #pragma unroll
    for (int c = 0; c < AF; c++) {
        float v = A[agr * K + acol + c];
        if (LNA) v = (v - amu) * ars * ln_s[acol + c] + ln_b[acol + c];
        pa[c] = v;
    }
    #pragma unroll
    for (int c = 0; c < WF; c++) pw[c] = W[wgr * K + wcol + c];
    #pragma unroll
    for (int c = 0; c < AF; c++) As[0][acol + c][arow] = pa[c];
    #pragma unroll
    for (int c = 0; c < WF; c++) Ws[0][wcol + c][wrow] = pw[c];
    __syncthreads();

    float acc[4][4];
    #pragma unroll
    for (int a = 0; a < 4; a++)
        #pragma unroll
        for (int b = 0; b < 4; b++) acc[a][b] = 0.0f;

    #pragma unroll 2
    for (int t = 0; t < NK; t++) {
        const int st = t & 1;
        if (t + 1 < NK) {
            const int k0 = (t + 1) * BK;
            #pragma unroll
            for (int c = 0; c < AF; c++) {
                float v = A[agr * K + k0 + acol + c];
                if (LNA) v = (v - amu) * ars * ln_s[k0 + acol + c] + ln_b[k0 + acol + c];
                pa[c] = v;
            }
            #pragma unroll
            for (int c = 0; c < WF; c++) pw[c] = W[wgr * K + k0 + wcol + c];
        }
        #pragma unroll
        for (int kk = 0; kk < BK; kk++) {
            float4 a4 = *reinterpret_cast<const float4*>(&As[st][kk][tm * 4]);
            float4 b4 = *reinterpret_cast<const float4*>(&Ws[st][kk][tn * 4]);
            float av[4] = {a4.x, a4.y, a4.z, a4.w};
            float bv[4] = {b4.x, b4.y, b4.z, b4.w};
            #pragma unroll
            for (int a = 0; a < 4; a++)
                #pragma unroll
                for (int b = 0; b < 4; b++) acc[a][b] += av[a] * bv[b];
        }
        if (t + 1 < NK) {
            const int ns = st ^ 1;
            #pragma unroll
            for (int c = 0; c < AF; c++) As[ns][acol + c][arow] = pa[c];
            #pragma unroll
            for (int c = 0; c < WF; c++) Ws[ns][wcol + c][wrow] = pw[c];
        }
        __syncthreads();
    }

    float vals[4][4];
    #pragma unroll
    for (int a = 0; a < 4; a++) {
        const int m = m0 + tm * 4 + a;
        #pragma unroll
        for (int b = 0; b < 4; b++) {
            const int n = n0 + tn * 4 + b;
            float v = acc[a][b] + bias[n];
            if (RELU) v = fmaxf(v, 0.0f);
            if (RES) v += g_x[m * NC + n];
            vals[a][b] = v;
        }
        float4 o = make_float4(vals[a][0], vals[a][1], vals[a][2], vals[a][3]);
        *reinterpret_cast<float4*>(&C[m * NC + (n0 + tn * 4)]) = o;
    }

    if (STATS) {
        #pragma unroll
        for (int a = 0; a < 4; a++) {
            float s = vals[a][0] + vals[a][1] + vals[a][2] + vals[a][3];
            float q = vals[a][0] * vals[a][0] + vals[a][1] * vals[a][1] +
                      vals[a][2] * vals[a][2] + vals[a][3] * vals[a][3];
            #pragma unroll
            for (int o = 16; o; o >>= 1) {
                s += __shfl_xor_sync(0xffffffffu, s, o);
                q += __shfl_xor_sync(0xffffffffu, q, o);
            }
            if ((tid & 31) == 0) {
                const int m = m0 + tm * 4 + a;
                float mean = s * (1.0f / NC);
                float var = q * (1.0f / NC) - mean * mean;
                g_mean[m] = mean;
                g_rstd[m] = rsqrtf(var + 1e-5f);
            }
        }
    }
}

// =================================================================================
// gemm3: BM=128 tile, 8xNR microtile with split 4+4 fragments (conflict-free LDS).
//   A = LN(g_x) on the fly. Used for qkv (BN=128,NR=8) and f1 (BN=64,NR=4).
// =================================================================================
template <int NC, int K, int BN, int NR, int RELU, int DST>
__global__ __launch_bounds__(256) void gemm3(
    const float* __restrict__ W, const float* __restrict__ bias,
    const float* __restrict__ ln_s, const float* __restrict__ ln_b) {

    constexpr int BM = 128;
    constexpr int NK = K / BK;
    constexpr int AF = BM * BK / 256;          // 8
    constexpr int WF = BN * BK / 256;          // 8 (BN=128) or 4 (BN=64)

    __shared__ float As[2][BK][BM + 4];
    __shared__ float Ws[2][BK][BN + 4];

    float* C = (DST == 1) ? g_qkv : g_ff;

    const int tid = threadIdx.x;
    const int m0 = blockIdx.y * BM, n0 = blockIdx.x * BN;
    const int tm = tid / 16, tn = tid % 16;

    const int arow = tid / 2;                  // 128 rows, 2 threads per row
    const int acol = (tid & 1) * AF;
    const int wrow = tid / (BK / WF);
    const int wcol = (tid % (BK / WF)) * WF;

    const int agr = m0 + arow;
    const int wgr = n0 + wrow;
    const float amu = g_mean[agr];
    const float ars = g_rstd[agr];

    float pa[AF], pw[WF];

    #pragma unroll
    for (int c = 0; c < AF; c++) {
        float v = g_x[agr * K + acol + c];
        pa[c] = (v - amu) * ars * ln_s[acol + c] + ln_b[acol + c];
    }
    #pragma unroll
    for (int c = 0; c < WF; c++) pw[c] = W[wgr * K + wcol + c];
    #pragma unroll
    for (int c = 0; c < AF; c++) As[0][acol + c][arow] = pa[c];
    #pragma unroll
    for (int c = 0; c < WF; c++) Ws[0][wcol + c][wrow] = pw[c];
    __syncthreads();

    float acc[8][NR];
    #pragma unroll
    for (int a = 0; a < 8; a++)
        #pragma unroll
        for (int b = 0; b < NR; b++) acc[a][b] = 0.0f;

    for (int t = 0; t < NK; t++) {
        const int st = t & 1;
        if (t + 1 < NK) {
            const int k0 = (t + 1) * BK;
            #pragma unroll
            for (int c = 0; c < AF; c++) {
                float v = g_x[agr * K + k0 + acol + c];
                pa[c] = (v - amu) * ars * ln_s[k0 + acol + c] + ln_b[k0 + acol + c];
            }
            #pragma unroll
            for (int c = 0; c < WF; c++) pw[c] = W[wgr * K + k0 + wcol + c];
        }
        #pragma unroll
        for (int kk = 0; kk < BK; kk++) {
            float av[8], bv[NR];
            float4 a0 = *reinterpret_cast<const float4*>(&As[st][kk][tm * 4]);
            float4 a1 = *reinterpret_cast<const float4*>(&As[st][kk][64 + tm * 4]);
            av[0] = a0.x; av[1] = a0.y; av[2] = a0.z; av[3] = a0.w;
            av[4] = a1.x; av[5] = a1.y; av[6] = a1.z; av[7] = a1.w;
            float4 b0 = *reinterpret_cast<const float4*>(&Ws[st][kk][tn * 4]);
            bv[0] = b0.x; bv[1] = b0.y; bv[2] = b0.z; bv[3] = b0.w;
            if (NR == 8) {
                float4 b1 = *reinterpret_cast<const float4*>(&Ws[st][kk][64 + tn * 4]);
                bv[4] = b1.x; bv[5] = b1.y; bv[6] = b1.z; bv[7] = b1.w;
            }
            #pragma unroll
            for (int a = 0; a < 8; a++)
                #pragma unroll
                for (int b = 0; b < NR; b++) acc[a][b] += av[a] * bv[b];
        }
        if (t + 1 < NK) {
            const int ns = st ^ 1;
            #pragma unroll
            for (int c = 0; c < AF; c++) As[ns][acol + c][arow] = pa[c];
            #pragma unroll
            for (int c = 0; c < WF; c++) Ws[ns][wcol + c][wrow] = pw[c];
        }
        __syncthreads();
    }

    // epilogue: rows tm*4 + (ra/4)*64 + ra%4 ; cols tn*4 + (b/4)*64 + b%4
    #pragma unroll
    for (int ra = 0; ra < 8; ra++) {
        const int m = m0 + tm * 4 + (ra / 4) * 64 + (ra % 4);
        #pragma unroll
        for (int half = 0; half < NR / 4; half++) {
            const int n = n0 + tn * 4 + half * 64;
            float v0 = acc[ra][half * 4 + 0] + bias[n + 0];
            float v1 = acc[ra][half * 4 + 1] + bias[n + 1];
            float v2 = acc[ra][half * 4 + 2] + bias[n + 2];
            float v3 = acc[ra][half * 4 + 3] + bias[n + 3];
            if (RELU) {
                v0 = fmaxf(v0, 0.0f); v1 = fmaxf(v1, 0.0f);
                v2 = fmaxf(v2, 0.0f); v3 = fmaxf(v3, 0.0f);
            }
            *reinterpret_cast<float4*>(&C[m * NC + n]) = make_float4(v0, v1, v2, v3);
        }
    }
}

// ---------------- sparse gather attention: one block per query, 128 threads ------
__global__ void attn_kernel() {
    int i = blockIdx.x;
    int hd = threadIdx.x;

    const float* qkv = g_qkv;
    float qv = qkv[i * QKVDIM + hd];
    int cnt = g_cnt[i];
    const int* nb = &g_nbr[i * MAXN];

    float m = -1e30f, ssum = 0.0f, acc = 0.0f;
    for (int n = 0; n < cnt; n++) {
        int j = nb[n];
        float kv = qkv[j * QKVDIM + HDIM + hd];
        float vv = qkv[j * QKVDIM + 2 * HDIM + hd];
        float p = qv * kv;
        p += __shfl_xor_sync(0xffffffffu, p, 8, 16);
        p += __shfl_xor_sync(0xffffffffu, p, 4, 16);
        p += __shfl_xor_sync(0xffffffffu, p, 2, 16);
        p += __shfl_xor_sync(0xffffffffu, p, 1, 16);
        float s = p * 0.25f;
        float nm = fmaxf(m, s);
        float corr = expf(m - nm);
        float e = expf(s - nm);
        ssum = ssum * corr + e;
        acc = acc * corr + e * vv;
        m = nm;
    }
    g_attn[i * HDIM + hd] = acc / ssum;
}

// ---------------- lat head ----------------
__global__ void lat_head_kernel(const float* __restrict__ w1, const float* __restrict__ b1,
                                const float* __restrict__ w2, const float* __restrict__ b2,
                                float* __restrict__ out) {
    int row = blockIdx.x;
    int tid = threadIdx.x;
    __shared__ float xs[HDIM];
    __shared__ float t1[HDIM];
    xs[tid] = g_x[row * HDIM + tid];
    __syncthreads();
    float acc = b1[tid];
    const float* wr = &w1[tid * HDIM];
    #pragma unroll 8
    for (int k = 0; k < HDIM; k++) acc += xs[k] * wr[k];
    t1[tid] = fmaxf(acc, 0.0f);
    __syncthreads();
    if (tid < LATD) {
        float a = b2[tid];
        const float* wr2 = &w2[tid * HDIM];
        #pragma unroll 8
        for (int k = 0; k < HDIM; k++) a += t1[k] * wr2[k];
        float q = a * a;
        q += __shfl_xor_sync(0xffffffffu, q, 8, 16);
        q += __shfl_xor_sync(0xffffffffu, q, 4, 16);
        q += __shfl_xor_sync(0xffffffffu, q, 2, 16);
        q += __shfl_xor_sync(0xffffffffu, q, 1, 16);
        float nrm = fmaxf(sqrtf(q), 1e-12f);
        out[row * LATD + tid] = a / nrm;
    }
}

// ---------------- beta head ----------------
__global__ void beta_head_kernel(const float* __restrict__ w1, const float* __restrict__ b1,
                                 const float* __restrict__ w2, const float* __restrict__ b2,
                                 float* __restrict__ out) {
    int row = blockIdx.x;
    int tid = threadIdx.x;
    __shared__ float xs[HDIM];
    xs[tid] = g_x[row * HDIM + tid];
    __syncthreads();
    float p = 0.0f;
    if (tid < 64) {
        float acc = b1[tid];
        const float* wr = &w1[tid * HDIM];
        #pragma unroll 8
        for (int k = 0; k < HDIM; k++) acc += xs[k] * wr[k];
        p = fmaxf(acc, 0.0f) * w2[tid];
    }
    #pragma unroll
    for (int o = 16; o; o >>= 1) p += __shfl_xor_sync(0xffffffffu, p, o);
    __shared__ float wsum[4];
    if ((tid & 31) == 0) wsum[tid >> 5] = p;
    __syncthreads();
    if (tid == 0) {
        float s = wsum[0] + wsum[1] + wsum[2] + wsum[3] + b2[0];
        float bta = 1.0f / (1.0f + expf(-s));
        bta = fminf(fmaxf(bta, 1e-6f), 1.0f - 1e-6f);
        out[row] = bta;
    }
}

// ---------------- launch ----------------
extern "C" void kernel_launch(void* const* d_in, const int* in_sizes, int n_in,
                              void* d_out, int out_size) {
    const float* x_raw = (const float*)d_in[0];
    const float* in_w  = (const float*)d_in[2];
    const float* in_b  = (const float*)d_in[3];
    const float* ln1_s = (const float*)d_in[4];
    const float* ln1_b = (const float*)d_in[5];
    const float* qkv_w = (const float*)d_in[6];
    const float* qkv_b = (const float*)d_in[7];
    const float* ao_w  = (const float*)d_in[8];
    const float* ao_b  = (const float*)d_in[9];
    const float* ln2_s = (const float*)d_in[10];
    const float* ln2_b = (const float*)d_in[11];
    const float* f1_w  = (const float*)d_in[12];
    const float* f1_b  = (const float*)d_in[13];
    const float* f2_w  = (const float*)d_in[14];
    const float* f2_b  = (const float*)d_in[15];
    const float* lat1_w = (const float*)d_in[16];
    const float* lat1_b = (const float*)d_in[17];
    const float* lat2_w = (const float*)d_in[18];
    const float* lat2_b = (const float*)d_in[19];
    const float* b1_w  = (const float*)d_in[20];
    const float* b1_b  = (const float*)d_in[21];
    const float* b2_w  = (const float*)d_in[22];
    const float* b2_b  = (const float*)d_in[23];
    float* out = (float*)d_out;

    // binned neighbor build
    zero_cells_kernel<<<(NCELL + 255) / 256, 256>>>();
    etaphi_bin_kernel<<<(NTOK + 255) / 256, 256>>>(x_raw);
    prefix_kernel<<<1, 1024>>>();
    scatter_kernel<<<(NTOK + 255) / 256, 256>>>();
    nbr_warp_kernel<<<NTOK / 8, 256>>>();

    // input projection + LN1(layer0) stats
    gemm2<NTOK, HDIM, 16, 32, 128, 0, 0, 0, 1, 0, 0>
        <<<dim3(1, NTOK / 32), 256>>>(x_raw, in_w, in_b, nullptr, nullptr);

    for (int l = 0; l < NLAYER; l++) {
        const float* l1s = ln1_s + l * HDIM;
        const float* l1b = ln1_b + l * HDIM;
        const float* qw  = qkv_w + l * QKVDIM * HDIM;
        const float* qb  = qkv_b + l * QKVDIM;
        const float* aw  = ao_w + l * HDIM * HDIM;
        const float* ab  = ao_b + l * HDIM;
        const float* l2s = ln2_s + l * HDIM;
        const float* l2b = ln2_b + l * HDIM;
        const float* w1  = f1_w + l * FFDIM * HDIM;
        const float* wb1 = f1_b + l * FFDIM;
        const float* w2  = f2_w + l * HDIM * FFDIM;
        const float* wb2 = f2_b + l * HDIM;

        // g_qkv = LN1(g_x) @ qw^T + qb   (128x128 tile, 8x8 microtile)
        gemm3<QKVDIM, HDIM, 128, 8, 0, 1>
            <<<dim3(QKVDIM / 128, NTOK / 128), 256>>>(qw, qb, l1s, l1b);

        attn_kernel<<<NTOK, HDIM>>>();

        // g_x += g_attn @ aw^T + ab ; epilogue -> LN2 stats
        gemm2<NTOK, HDIM, HDIM, 32, 128, 0, 0, 1, 1, 2, 0>
            <<<dim3(1, NTOK / 32), 256>>>(nullptr, aw, ab, nullptr, nullptr);

        // g_ff = relu(LN2(g_x) @ w1^T + wb1)   (128x64 tile, 8x4 microtile)
        gemm3<FFDIM, HDIM, 64, 4, 1, 2>
            <<<dim3(FFDIM / 64, NTOK / 128), 256>>>(w1, wb1, l2s, l2b);

        // g_x += g_ff @ w2^T + wb2 ; epilogue -> next-layer LN1 stats
        gemm2<NTOK, HDIM, FFDIM, 32, 128, 0, 0, 1, 1, 3, 0>
            <<<dim3(1, NTOK / 32), 256>>>(nullptr, w2, wb2, nullptr, nullptr);
    }

    beta_head_kernel<<<NTOK, HDIM>>>(b1_w, b1_b, b2_w, b2_b, out);
    lat_head_kernel<<<NTOK, HDIM>>>(lat1_w, lat1_b, lat2_w, lat2_b, out + NTOK);
}